// round 8
// baseline (speedup 1.0000x reference)
#include <cuda_runtime.h>
#include <math.h>
#include <stdint.h>

#define N_NODES 100000
#define F_IN    500
#define F_HID   256
#define F_OUT   40
#define N_EDGES 1600000
#define K_ITERS 10

constexpr float LAMBDA_AMP = 0.5f;
constexpr float GAMMA_ = 1.0f / (2.0f * (1.0f - LAMBDA_AMP));   // 1.0
constexpr float COEF   = GAMMA_ * 2.0f * (1.0f - LAMBDA_AMP);   // 1.0
constexpr float LAM    = GAMMA_ * LAMBDA_AMP;                   // 0.5

// ---------------- device scratch (no allocations allowed) ----------------
__device__ __align__(16) float g_part_h[(size_t)4 * N_NODES * F_OUT];
__device__ __align__(16) float g_h [(size_t)N_NODES * F_OUT];   // hh = MLP output
__device__ __align__(16) float g_xa[(size_t)N_NODES * F_OUT];
__device__ __align__(16) float g_xb[(size_t)N_NODES * F_OUT];
__device__ int    g_count[N_NODES];
__device__ int    g_rowstart[N_NODES];
__device__ int    g_cursor[N_NODES];
__device__ float  g_dinv[N_NODES];
__device__ __align__(16) float2 g_csr_sw[N_EDGES];   // {src_bits, weight}
__device__ int    g_part[512];
__device__ int    g_pscan[512];

// ---------------- setup kernels ----------------
__global__ void zero_kernel() {
    int i = blockIdx.x * blockDim.x + threadIdx.x;
    if (i < N_NODES) { g_count[i] = 0; g_cursor[i] = 0; }
}

__global__ void hist_kernel(const int* __restrict__ dst) {
    for (int e = blockIdx.x * blockDim.x + threadIdx.x; e < N_EDGES;
         e += gridDim.x * blockDim.x)
        atomicAdd(&g_count[dst[e]], 1);
}

__global__ void dinv_kernel() {
    int i = blockIdx.x * blockDim.x + threadIdx.x;
    if (i < N_NODES) {
        float deg = (float)(g_count[i] + 1);   // +1 self loop
        g_dinv[i] = rsqrtf(deg);
    }
}

// exclusive scan: 512 elems/block (2 per thread), block totals to partials
__global__ void scan_block(const int* __restrict__ in, int* __restrict__ out,
                           int* __restrict__ partials, int n) {
    int t = threadIdx.x, lane = t & 31, w = t >> 5;
    int g = blockIdx.x * 512 + 2 * t;
    int v0 = (g     < n) ? in[g]     : 0;
    int v1 = (g + 1 < n) ? in[g + 1] : 0;
    int s = v0 + v1;
    int x = s;
#pragma unroll
    for (int o = 1; o < 32; o <<= 1) {
        int y = __shfl_up_sync(0xffffffffu, x, o);
        if (lane >= o) x += y;
    }
    __shared__ int wsum[8];
    if (lane == 31) wsum[w] = x;
    __syncthreads();
    if (w == 0) {
        int ws = (lane < 8) ? wsum[lane] : 0;
#pragma unroll
        for (int o = 1; o < 8; o <<= 1) {
            int y = __shfl_up_sync(0xffffffffu, ws, o);
            if (lane >= o) ws += y;
        }
        if (lane < 8) wsum[lane] = ws;
    }
    __syncthreads();
    int base = (w > 0) ? wsum[w - 1] : 0;
    int excl = base + x - s;
    if (g     < n) out[g]     = excl;
    if (g + 1 < n) out[g + 1] = excl + v0;
    if (t == 255) partials[blockIdx.x] = base + x;
}

__global__ void add_offsets(int* __restrict__ out, const int* __restrict__ pscan, int n) {
    int i = blockIdx.x * blockDim.x + threadIdx.x;
    if (i < n) out[i] += pscan[i >> 9];
}

__global__ void scatter_kernel(const int* __restrict__ src, const int* __restrict__ dst) {
    for (int e = blockIdx.x * blockDim.x + threadIdx.x; e < N_EDGES;
         e += gridDim.x * blockDim.x) {
        int d = dst[e], s = src[e];
        int pos = g_rowstart[d] + atomicAdd(&g_cursor[d], 1);
        g_csr_sw[pos] = make_float2(__int_as_float(s), g_dinv[s] * g_dinv[d]);
    }
}

// ---------------- fused MLP (tf32 mma.sync): round-5 proven version ----------
// Phase 1: BM=128 BN=64 BK=32, 256 threads = 8 warps (4M x 2N), warp tile 32x32
// Phase 2: relu tile (tf32, smem) @ W2 slice (64x40) -> per-bn partial of h
#define BM 128
#define BN 64
#define BK 32

__device__ __forceinline__ uint32_t f2tf32(float f) {
    uint32_t r;
    asm("cvt.rna.tf32.f32 %0, %1;" : "=r"(r) : "f"(f));
    return r;
}

#define AS_STRIDE 36
#define BS_STRIDE 68
#define HT_STRIDE 68
#define W2_STRIDE 68
#define SMEM_WORDS (8704 + 40 * W2_STRIDE)

__global__ __launch_bounds__(256) void gemm1_mma_kernel(const float* __restrict__ A,
                                                        const float* __restrict__ B,
                                                        const float* __restrict__ bias,
                                                        const float* __restrict__ W2) {
    __shared__ __align__(16) uint32_t smem_u[SMEM_WORDS];
    uint32_t* As = smem_u;                     // [128][36]
    uint32_t* Bs = smem_u + 128 * AS_STRIDE;   // [32][68]

    int bm = blockIdx.y * BM, bn = blockIdx.x * BN;
    int tid = threadIdx.x;
    int warpId = tid >> 5, lane = tid & 31;
    int warpM = warpId & 3;
    int warpN = warpId >> 2;
    int group = lane >> 2;
    int tig   = lane & 3;

    float acc[2][4][4] = {};

    for (int k0 = 0; k0 < 512; k0 += BK) {
#pragma unroll
        for (int i = 0; i < 4; i++) {
            int idx = tid + i * 256;
            int r = idx >> 3, q = idx & 7;
            int gm = bm + r, gk = k0 + q * 4;
            float4 v = make_float4(0.f, 0.f, 0.f, 0.f);
            if (gm < N_NODES && gk < F_IN)
                v = *(const float4*)(A + (size_t)gm * F_IN + gk);
            As[r * AS_STRIDE + q * 4 + 0] = f2tf32(v.x);
            As[r * AS_STRIDE + q * 4 + 1] = f2tf32(v.y);
            As[r * AS_STRIDE + q * 4 + 2] = f2tf32(v.z);
            As[r * AS_STRIDE + q * 4 + 3] = f2tf32(v.w);
        }
#pragma unroll
        for (int i = 0; i < 2; i++) {
            int idx = tid + i * 256;
            int kk = idx >> 4, c4 = idx & 15;
            int gk = k0 + kk;
            float4 v = make_float4(0.f, 0.f, 0.f, 0.f);
            if (gk < F_IN)
                v = *(const float4*)(B + (size_t)gk * F_HID + bn + c4 * 4);
            Bs[kk * BS_STRIDE + c4 * 4 + 0] = f2tf32(v.x);
            Bs[kk * BS_STRIDE + c4 * 4 + 1] = f2tf32(v.y);
            Bs[kk * BS_STRIDE + c4 * 4 + 2] = f2tf32(v.z);
            Bs[kk * BS_STRIDE + c4 * 4 + 3] = f2tf32(v.w);
        }
        __syncthreads();

#pragma unroll
        for (int ks = 0; ks < BK / 8; ks++) {
            int kb = ks * 8;
            uint32_t af[2][4];
#pragma unroll
            for (int mi = 0; mi < 2; mi++) {
                int r0 = warpM * 32 + mi * 16 + group;
                af[mi][0] = As[r0 * AS_STRIDE + kb + tig];
                af[mi][1] = As[(r0 + 8) * AS_STRIDE + kb + tig];
                af[mi][2] = As[r0 * AS_STRIDE + kb + tig + 4];
                af[mi][3] = As[(r0 + 8) * AS_STRIDE + kb + tig + 4];
            }
            uint32_t bf[4][2];
#pragma unroll
            for (int ni = 0; ni < 4; ni++) {
                int c0 = warpN * 32 + ni * 8 + group;
                bf[ni][0] = Bs[(kb + tig) * BS_STRIDE + c0];
                bf[ni][1] = Bs[(kb + tig + 4) * BS_STRIDE + c0];
            }
#pragma unroll
            for (int mi = 0; mi < 2; mi++)
#pragma unroll
                for (int ni = 0; ni < 4; ni++) {
                    asm volatile(
                        "mma.sync.aligned.m16n8k8.row.col.f32.tf32.tf32.f32 "
                        "{%0,%1,%2,%3}, {%4,%5,%6,%7}, {%8,%9}, {%0,%1,%2,%3};"
                        : "+f"(acc[mi][ni][0]), "+f"(acc[mi][ni][1]),
                          "+f"(acc[mi][ni][2]), "+f"(acc[mi][ni][3])
                        : "r"(af[mi][0]), "r"(af[mi][1]), "r"(af[mi][2]), "r"(af[mi][3]),
                          "r"(bf[ni][0]), "r"(bf[ni][1]));
                }
        }
        __syncthreads();
    }

    // ---- phase 2: relu tile -> smem (tf32), W2 slice -> smem, second mma ----
    uint32_t* Ht  = smem_u;            // [128][HT_STRIDE]
    uint32_t* W2s = smem_u + 8704;     // [40][W2_STRIDE]

#pragma unroll
    for (int mi = 0; mi < 2; mi++) {
#pragma unroll
        for (int ni = 0; ni < 4; ni++) {
            int lc = warpN * 32 + ni * 8 + tig * 2;
            float bz0 = bias[bn + lc], bz1 = bias[bn + lc + 1];
            int r0 = warpM * 32 + mi * 16 + group;
            Ht[r0 * HT_STRIDE + lc]     = f2tf32(fmaxf(acc[mi][ni][0] + bz0, 0.f));
            Ht[r0 * HT_STRIDE + lc + 1] = f2tf32(fmaxf(acc[mi][ni][1] + bz1, 0.f));
            int r1 = r0 + 8;
            Ht[r1 * HT_STRIDE + lc]     = f2tf32(fmaxf(acc[mi][ni][2] + bz0, 0.f));
            Ht[r1 * HT_STRIDE + lc + 1] = f2tf32(fmaxf(acc[mi][ni][3] + bz1, 0.f));
        }
    }
    for (int idx = tid; idx < 40 * 64; idx += 256) {
        int n = idx >> 6, kk = idx & 63;
        W2s[n * W2_STRIDE + kk] = f2tf32(W2[(size_t)(bn + kk) * F_OUT + n]);
    }
    __syncthreads();

    float acc2[5][4] = {};
    int wrow = warpId * 16;
#pragma unroll
    for (int ks = 0; ks < 8; ks++) {
        int kb = ks * 8;
        uint32_t af[4];
        af[0] = Ht[(wrow + group) * HT_STRIDE + kb + tig];
        af[1] = Ht[(wrow + 8 + group) * HT_STRIDE + kb + tig];
        af[2] = Ht[(wrow + group) * HT_STRIDE + kb + tig + 4];
        af[3] = Ht[(wrow + 8 + group) * HT_STRIDE + kb + tig + 4];
#pragma unroll
        for (int ni = 0; ni < 5; ni++) {
            uint32_t b0 = W2s[(ni * 8 + group) * W2_STRIDE + kb + tig];
            uint32_t b1 = W2s[(ni * 8 + group) * W2_STRIDE + kb + tig + 4];
            asm volatile(
                "mma.sync.aligned.m16n8k8.row.col.f32.tf32.tf32.f32 "
                "{%0,%1,%2,%3}, {%4,%5,%6,%7}, {%8,%9}, {%0,%1,%2,%3};"
                : "+f"(acc2[ni][0]), "+f"(acc2[ni][1]),
                  "+f"(acc2[ni][2]), "+f"(acc2[ni][3])
                : "r"(af[0]), "r"(af[1]), "r"(af[2]), "r"(af[3]),
                  "r"(b0), "r"(b1));
        }
    }

    float* part = g_part_h + (size_t)blockIdx.x * N_NODES * F_OUT;
#pragma unroll
    for (int ni = 0; ni < 5; ni++) {
        int col = ni * 8 + tig * 2;
        int r0 = bm + wrow + group;
        if (r0 < N_NODES)
            *(float2*)(part + (size_t)r0 * F_OUT + col) =
                make_float2(acc2[ni][0], acc2[ni][1]);
        int r1 = r0 + 8;
        if (r1 < N_NODES)
            *(float2*)(part + (size_t)r1 * F_OUT + col) =
                make_float2(acc2[ni][2], acc2[ni][3]);
    }
}

// ---------------- combine: h = b2 + sum of 4 partials (deterministic) --------
__global__ __launch_bounds__(256) void combine_kernel(const float* __restrict__ b2) {
    int idx = blockIdx.x * 256 + threadIdx.x;
    const int TOT = N_NODES * F_OUT / 4;
    if (idx >= TOT) return;
    const float4* p = (const float4*)g_part_h;
    const size_t STRIDE4 = (size_t)N_NODES * F_OUT / 4;
    float4 a = p[idx];
    float4 b = p[idx + STRIDE4];
    float4 c = p[idx + 2 * STRIDE4];
    float4 d = p[idx + 3 * STRIDE4];
    float4 bz = ((const float4*)b2)[idx % (F_OUT / 4)];
    float4 r;
    r.x = a.x + b.x + c.x + d.x + bz.x;
    r.y = a.y + b.y + c.y + d.y + bz.y;
    r.z = a.z + b.z + c.z + d.z + bz.z;
    r.w = a.w + b.w + c.w + d.w + bz.w;
    ((float4*)g_h)[idx] = r;
}

// ---------------- AMP: warp per node, 3 edge-groups of 10 lanes, float4 ----
__global__ __launch_bounds__(256) void amp_kernel(const float4* __restrict__ xk4,
                                                  float4* __restrict__ xout4,
                                                  float* __restrict__ sout) {
    int node = (blockIdx.x * 256 + threadIdx.x) >> 5;
    int lane = threadIdx.x & 31;
    if (node >= N_NODES) return;
    int g = lane >= 30 ? 3 : (lane >= 20 ? 2 : (lane >= 10 ? 1 : 0));
    int sub = lane - g * 10;
    if (g == 3) sub = lane - 30;
    bool act = lane < 30;

    float4 xq = make_float4(0.f, 0.f, 0.f, 0.f);
    float4 accA = make_float4(0.f, 0.f, 0.f, 0.f);
    float4 accB = make_float4(0.f, 0.f, 0.f, 0.f);
    if (g == 0) {
        xq = xk4[(size_t)node * 10 + sub];
        float dv = g_dinv[node];
        float wself = dv * dv;
        accA.x = wself * xq.x; accA.y = wself * xq.y;
        accA.z = wself * xq.z; accA.w = wself * xq.w;
    }

    int beg = g_rowstart[node];
    int cnt = g_count[node];
    int base = 0;
    for (; base + 6 <= cnt; base += 6) {
        int iA = base + g, iB = base + 3 + g;
        float2 swA = act ? g_csr_sw[beg + iA] : make_float2(0.f, 0.f);
        float2 swB = act ? g_csr_sw[beg + iB] : make_float2(0.f, 0.f);
        int sA = act ? __float_as_int(swA.x) : 0;
        int sB = act ? __float_as_int(swB.x) : 0;
        float4 xA = xk4[(size_t)sA * 10 + sub];
        float4 xB = xk4[(size_t)sB * 10 + sub];
        accA.x += swA.y * xA.x; accA.y += swA.y * xA.y;
        accA.z += swA.y * xA.z; accA.w += swA.y * xA.w;
        accB.x += swB.y * xB.x; accB.y += swB.y * xB.y;
        accB.z += swB.y * xB.z; accB.w += swB.y * xB.w;
    }
    for (; base < cnt; base += 3) {
        int idx = base + g;
        bool v = act && (idx < cnt);
        float2 sw = v ? g_csr_sw[beg + idx] : make_float2(0.f, 0.f);
        int s = v ? __float_as_int(sw.x) : 0;
        float4 xs = xk4[(size_t)s * 10 + sub];
        accA.x += sw.y * xs.x; accA.y += sw.y * xs.y;
        accA.z += sw.y * xs.z; accA.w += sw.y * xs.w;
    }
    accA.x += accB.x; accA.y += accB.y; accA.z += accB.z; accA.w += accB.w;

    // combine the 3 groups into lanes 0-9
    {
        float t1, t2;
        t1 = __shfl_down_sync(0xffffffffu, accA.x, 10);
        t2 = __shfl_down_sync(0xffffffffu, accA.x, 20);
        accA.x += t1 + t2;
        t1 = __shfl_down_sync(0xffffffffu, accA.y, 10);
        t2 = __shfl_down_sync(0xffffffffu, accA.y, 20);
        accA.y += t1 + t2;
        t1 = __shfl_down_sync(0xffffffffu, accA.z, 10);
        t2 = __shfl_down_sync(0xffffffffu, accA.z, 20);
        accA.z += t1 + t2;
        t1 = __shfl_down_sync(0xffffffffu, accA.w, 10);
        t2 = __shfl_down_sync(0xffffffffu, accA.w, 20);
        accA.w += t1 + t2;
    }

    float4 hq = make_float4(0.f, 0.f, 0.f, 0.f);
    float4 d = make_float4(0.f, 0.f, 0.f, 0.f);
    float ss = 0.f;
    if (g == 0) {
        hq = ((const float4*)g_h)[(size_t)node * 10 + sub];
        float4 y;
        y.x = xq.x - COEF * (xq.x - accA.x);
        y.y = xq.y - COEF * (xq.y - accA.y);
        y.z = xq.z - COEF * (xq.z - accA.z);
        y.w = xq.w - COEF * (xq.w - accA.w);
        d.x = y.x - hq.x; d.y = y.y - hq.y; d.z = y.z - hq.z; d.w = y.w - hq.w;
        ss = d.x * d.x + d.y * d.y + d.z * d.z + d.w * d.w;
    }
#pragma unroll
    for (int o = 16; o > 0; o >>= 1) ss += __shfl_xor_sync(0xffffffffu, ss, o);
    float rn = sqrtf(ss);
    float score = (rn > 0.f) ? fmaxf(rn - LAM, 0.f) / rn : 0.f;

    if (g == 0) {
        float4 r;
        r.x = hq.x + score * d.x; r.y = hq.y + score * d.y;
        r.z = hq.z + score * d.z; r.w = hq.w + score * d.w;
        xout4[(size_t)node * 10 + sub] = r;
    }
    if (sout && lane == 0) sout[node] = score;
}

// ---------------- log_softmax: warp per row ----------------
__global__ __launch_bounds__(256) void finalize_kernel(const float* __restrict__ xk,
                                                       float* __restrict__ out) {
    int row = (blockIdx.x * 256 + threadIdx.x) >> 5;
    int lane = threadIdx.x & 31;
    if (row >= N_NODES) return;
    const float* xr = xk + (size_t)row * F_OUT;
    float v0 = xr[lane];
    bool has1 = (lane + 32 < F_OUT);
    float v1 = has1 ? xr[lane + 32] : -INFINITY;
    float m = fmaxf(v0, v1);
#pragma unroll
    for (int o = 16; o > 0; o >>= 1) m = fmaxf(m, __shfl_xor_sync(0xffffffffu, m, o));
    float e = expf(v0 - m) + (has1 ? expf(v1 - m) : 0.f);
#pragma unroll
    for (int o = 16; o > 0; o >>= 1) e += __shfl_xor_sync(0xffffffffu, e, o);
    float lse = m + logf(e);
    out[(size_t)row * F_OUT + lane] = v0 - lse;
    if (has1) out[(size_t)row * F_OUT + 32 + lane] = v1 - lse;
}

// ---------------- launch ----------------
extern "C" void kernel_launch(void* const* d_in, const int* in_sizes, int n_in,
                              void* d_out, int out_size) {
    const float* x   = (const float*)d_in[0];
    const float* W1  = (const float*)d_in[1];
    const float* b1  = (const float*)d_in[2];
    const float* W2  = (const float*)d_in[3];
    const float* b2  = (const float*)d_in[4];
    const int* esrc  = (const int*)d_in[5];
    const int* edst  = (const int*)d_in[6];
    float* out = (float*)d_out;

    float *ph, *pxa, *pxb;
    int *pcount, *prowstart, *ppart, *ppscan;
    cudaGetSymbolAddress((void**)&ph,  g_h);
    cudaGetSymbolAddress((void**)&pxa, g_xa);
    cudaGetSymbolAddress((void**)&pxb, g_xb);
    cudaGetSymbolAddress((void**)&pcount,    g_count);
    cudaGetSymbolAddress((void**)&prowstart, g_rowstart);
    cudaGetSymbolAddress((void**)&ppart,     g_part);
    cudaGetSymbolAddress((void**)&ppscan,    g_pscan);

    const int NB = (N_NODES + 255) / 256;

    zero_kernel<<<NB, 256>>>();
    hist_kernel<<<1024, 256>>>(edst);
    dinv_kernel<<<NB, 256>>>();

    // slot 4: fused MLP (profiled)
    dim3 g1grid(F_HID / BN, (N_NODES + BM - 1) / BM);
    gemm1_mma_kernel<<<g1grid, 256>>>(x, W1, b1, W2);

    const int SCAN_BLOCKS = (N_NODES + 511) / 512;
    scan_block<<<SCAN_BLOCKS, 256>>>(pcount, prowstart, ppart, N_NODES);
    scan_block<<<1, 256>>>(ppart, ppscan, ppart, SCAN_BLOCKS);
    add_offsets<<<NB, 256>>>(prowstart, ppscan, N_NODES);
    scatter_kernel<<<1024, 256>>>(esrc, edst);

    combine_kernel<<<(N_NODES * F_OUT / 4 + 255) / 256, 256>>>(b2);

    float* score_out = nullptr;
    float* lsm_out = out;
    if (out_size >= N_NODES * F_OUT + N_NODES) {
        score_out = out + (size_t)N_NODES * F_OUT;
    } else if (out_size == N_NODES) {
        score_out = out;
        lsm_out = nullptr;
    }

    const int AMP_BLOCKS = (N_NODES * 32 + 255) / 256;
    const float* xin = ph;
    float* bufs[2] = {pxa, pxb};
    for (int it = 0; it < K_ITERS; it++) {
        float* xout = bufs[it & 1];
        float* so = (it == K_ITERS - 1) ? score_out : nullptr;
        amp_kernel<<<AMP_BLOCKS, 256>>>((const float4*)xin, (float4*)xout, so);
        xin = xout;
    }

    if (lsm_out)
        finalize_kernel<<<AMP_BLOCKS, 256>>>(xin, lsm_out);
}

// round 9
// speedup vs baseline: 1.0915x; 1.0915x over previous
#include <cuda_runtime.h>
#include <math.h>
#include <stdint.h>

#define N_NODES 100000
#define F_IN    500
#define F_HID   256
#define F_OUT   40
#define N_EDGES 1600000
#define K_ITERS 10

constexpr float LAMBDA_AMP = 0.5f;
constexpr float GAMMA_ = 1.0f / (2.0f * (1.0f - LAMBDA_AMP));   // 1.0
constexpr float COEF   = GAMMA_ * 2.0f * (1.0f - LAMBDA_AMP);   // 1.0
constexpr float LAM    = GAMMA_ * LAMBDA_AMP;                   // 0.5

// ---------------- device scratch (no allocations allowed) ----------------
__device__ __align__(16) float g_part_h[(size_t)2 * N_NODES * F_OUT];
__device__ __align__(16) float g_h [(size_t)N_NODES * F_OUT];
__device__ __align__(16) float g_xa[(size_t)N_NODES * F_OUT];
__device__ __align__(16) float g_xb[(size_t)N_NODES * F_OUT];
__device__ int    g_count[N_NODES];
__device__ int    g_rowstart[N_NODES];
__device__ int    g_cursor[N_NODES];
__device__ float  g_dinv[N_NODES];
__device__ __align__(16) float2 g_csr_sw[N_EDGES];   // {src_bits, weight}
__device__ int    g_part[512];
__device__ int    g_pscan[512];

// ---------------- setup kernels ----------------
__global__ void zero_kernel() {
    int i = blockIdx.x * blockDim.x + threadIdx.x;
    if (i < N_NODES) { g_count[i] = 0; g_cursor[i] = 0; }
}

__global__ void hist_kernel(const int* __restrict__ dst) {
    for (int e = blockIdx.x * blockDim.x + threadIdx.x; e < N_EDGES;
         e += gridDim.x * blockDim.x)
        atomicAdd(&g_count[dst[e]], 1);
}

__global__ void dinv_kernel() {
    int i = blockIdx.x * blockDim.x + threadIdx.x;
    if (i < N_NODES) {
        float deg = (float)(g_count[i] + 1);
        g_dinv[i] = rsqrtf(deg);
    }
}

__global__ void scan_block(const int* __restrict__ in, int* __restrict__ out,
                           int* __restrict__ partials, int n) {
    int t = threadIdx.x, lane = t & 31, w = t >> 5;
    int g = blockIdx.x * 512 + 2 * t;
    int v0 = (g     < n) ? in[g]     : 0;
    int v1 = (g + 1 < n) ? in[g + 1] : 0;
    int s = v0 + v1;
    int x = s;
#pragma unroll
    for (int o = 1; o < 32; o <<= 1) {
        int y = __shfl_up_sync(0xffffffffu, x, o);
        if (lane >= o) x += y;
    }
    __shared__ int wsum[8];
    if (lane == 31) wsum[w] = x;
    __syncthreads();
    if (w == 0) {
        int ws = (lane < 8) ? wsum[lane] : 0;
#pragma unroll
        for (int o = 1; o < 8; o <<= 1) {
            int y = __shfl_up_sync(0xffffffffu, ws, o);
            if (lane >= o) ws += y;
        }
        if (lane < 8) wsum[lane] = ws;
    }
    __syncthreads();
    int base = (w > 0) ? wsum[w - 1] : 0;
    int excl = base + x - s;
    if (g     < n) out[g]     = excl;
    if (g + 1 < n) out[g + 1] = excl + v0;
    if (t == 255) partials[blockIdx.x] = base + x;
}

__global__ void add_offsets(int* __restrict__ out, const int* __restrict__ pscan, int n) {
    int i = blockIdx.x * blockDim.x + threadIdx.x;
    if (i < n) out[i] += pscan[i >> 9];
}

__global__ void scatter_kernel(const int* __restrict__ src, const int* __restrict__ dst) {
    for (int e = blockIdx.x * blockDim.x + threadIdx.x; e < N_EDGES;
         e += gridDim.x * blockDim.x) {
        int d = dst[e], s = src[e];
        int pos = g_rowstart[d] + atomicAdd(&g_cursor[d], 1);
        g_csr_sw[pos] = make_float2(__int_as_float(s), g_dinv[s] * g_dinv[d]);
    }
}

// ---------------- fused MLP (tf32 mma.sync), big tiles ----------------
// BM=256 BN=128 BK=32, 8 warps (4M x 2N), warp tile 64x64 -> 128B smem per mma
#define BM 256
#define BN 128
#define BK 32
#define AS_STRIDE 36
#define BS_STRIDE 136
#define HT_STRIDE 136
#define W2_STRIDE 136
// word offsets: phase1 As[256][36]@0, Bs[32][136]@9216 (end 13568)
// phase2 Ht[256][136]@0, W2s[40][136]@34816 (end 40256)
#define DSMEM_BYTES (40256 * 4)

__device__ __forceinline__ uint32_t f2tf32(float f) {
    uint32_t r;
    asm("cvt.rna.tf32.f32 %0, %1;" : "=r"(r) : "f"(f));
    return r;
}

__global__ __launch_bounds__(256, 1) void gemm1_mma_kernel(const float* __restrict__ A,
                                                           const float* __restrict__ B,
                                                           const float* __restrict__ bias,
                                                           const float* __restrict__ W2) {
    extern __shared__ __align__(16) uint32_t smem_u[];
    uint32_t* As = smem_u;            // [256][36]
    uint32_t* Bs = smem_u + 9216;     // [32][136]

    int bm = blockIdx.y * BM, bn = blockIdx.x * BN;
    int tid = threadIdx.x;
    int warpId = tid >> 5, lane = tid & 31;
    int warpM = warpId & 3;           // 0..3 -> 64-row slice
    int warpN = warpId >> 2;          // 0..1 -> 64-col slice
    int group = lane >> 2;            // 0..7
    int tig   = lane & 3;             // 0..3

    float acc[4][8][4] = {};

    for (int k0 = 0; k0 < 512; k0 += BK) {
        // stage A: 256 rows x 32 k, uint4 stores
#pragma unroll
        for (int i = 0; i < 8; i++) {
            int idx = tid + i * 256;
            int r = idx >> 3, q = idx & 7;
            int gm = bm + r, gk = k0 + q * 4;
            float4 v = make_float4(0.f, 0.f, 0.f, 0.f);
            if (gm < N_NODES && gk < F_IN)
                v = *(const float4*)(A + (size_t)gm * F_IN + gk);
            uint4 t = make_uint4(f2tf32(v.x), f2tf32(v.y), f2tf32(v.z), f2tf32(v.w));
            *(uint4*)(As + r * AS_STRIDE + q * 4) = t;
        }
        // stage B: 32 k x 128 cols
#pragma unroll
        for (int i = 0; i < 4; i++) {
            int idx = tid + i * 256;
            int kk = idx >> 5, c4 = idx & 31;
            int gk = k0 + kk;
            float4 v = make_float4(0.f, 0.f, 0.f, 0.f);
            if (gk < F_IN)
                v = *(const float4*)(B + (size_t)gk * F_HID + bn + c4 * 4);
            uint4 t = make_uint4(f2tf32(v.x), f2tf32(v.y), f2tf32(v.z), f2tf32(v.w));
            *(uint4*)(Bs + kk * BS_STRIDE + c4 * 4) = t;
        }
        __syncthreads();

#pragma unroll
        for (int ks = 0; ks < BK / 8; ks++) {
            int kb = ks * 8;
            uint32_t af[4][4];
#pragma unroll
            for (int mi = 0; mi < 4; mi++) {
                int r0 = warpM * 64 + mi * 16 + group;
                af[mi][0] = As[r0 * AS_STRIDE + kb + tig];
                af[mi][1] = As[(r0 + 8) * AS_STRIDE + kb + tig];
                af[mi][2] = As[r0 * AS_STRIDE + kb + tig + 4];
                af[mi][3] = As[(r0 + 8) * AS_STRIDE + kb + tig + 4];
            }
            uint32_t bf[8][2];
#pragma unroll
            for (int ni = 0; ni < 8; ni++) {
                int c0 = warpN * 64 + ni * 8 + group;
                bf[ni][0] = Bs[(kb + tig) * BS_STRIDE + c0];
                bf[ni][1] = Bs[(kb + tig + 4) * BS_STRIDE + c0];
            }
#pragma unroll
            for (int mi = 0; mi < 4; mi++)
#pragma unroll
                for (int ni = 0; ni < 8; ni++) {
                    asm volatile(
                        "mma.sync.aligned.m16n8k8.row.col.f32.tf32.tf32.f32 "
                        "{%0,%1,%2,%3}, {%4,%5,%6,%7}, {%8,%9}, {%0,%1,%2,%3};"
                        : "+f"(acc[mi][ni][0]), "+f"(acc[mi][ni][1]),
                          "+f"(acc[mi][ni][2]), "+f"(acc[mi][ni][3])
                        : "r"(af[mi][0]), "r"(af[mi][1]), "r"(af[mi][2]), "r"(af[mi][3]),
                          "r"(bf[ni][0]), "r"(bf[ni][1]));
                }
        }
        __syncthreads();
    }

    // ---- phase 2: relu tile -> Ht (tf32), W2 slice -> smem, second mma ----
    uint32_t* Ht  = smem_u;            // [256][136]
    uint32_t* W2s = smem_u + 34816;    // [40][136]

#pragma unroll
    for (int mi = 0; mi < 4; mi++) {
#pragma unroll
        for (int ni = 0; ni < 8; ni++) {
            int lc = warpN * 64 + ni * 8 + tig * 2;
            float bz0 = bias[bn + lc], bz1 = bias[bn + lc + 1];
            int r0 = warpM * 64 + mi * 16 + group;
            Ht[r0 * HT_STRIDE + lc]     = f2tf32(fmaxf(acc[mi][ni][0] + bz0, 0.f));
            Ht[r0 * HT_STRIDE + lc + 1] = f2tf32(fmaxf(acc[mi][ni][1] + bz1, 0.f));
            int r1 = r0 + 8;
            Ht[r1 * HT_STRIDE + lc]     = f2tf32(fmaxf(acc[mi][ni][2] + bz0, 0.f));
            Ht[r1 * HT_STRIDE + lc + 1] = f2tf32(fmaxf(acc[mi][ni][3] + bz1, 0.f));
        }
    }
    // W2 slice: W2s[n][kk] = W2[(bn+kk)*40 + n], 40 x 128
    for (int idx = tid; idx < 40 * 128; idx += 256) {
        int n = idx >> 7, kk = idx & 127;
        W2s[n * W2_STRIDE + kk] = f2tf32(W2[(size_t)(bn + kk) * F_OUT + n]);
    }
    __syncthreads();

    // second mma: each warp owns 32 rows (mi=2), N=40 (5 tiles), K=128 local
    float acc2[2][5][4] = {};
    int wrow = warpId * 32;
#pragma unroll
    for (int ks = 0; ks < 16; ks++) {
        int kb = ks * 8;
        uint32_t af[2][4];
#pragma unroll
        for (int mi = 0; mi < 2; mi++) {
            int r0 = wrow + mi * 16 + group;
            af[mi][0] = Ht[r0 * HT_STRIDE + kb + tig];
            af[mi][1] = Ht[(r0 + 8) * HT_STRIDE + kb + tig];
            af[mi][2] = Ht[r0 * HT_STRIDE + kb + tig + 4];
            af[mi][3] = Ht[(r0 + 8) * HT_STRIDE + kb + tig + 4];
        }
#pragma unroll
        for (int ni = 0; ni < 5; ni++) {
            uint32_t b0 = W2s[(ni * 8 + group) * W2_STRIDE + kb + tig];
            uint32_t b1 = W2s[(ni * 8 + group) * W2_STRIDE + kb + tig + 4];
#pragma unroll
            for (int mi = 0; mi < 2; mi++) {
                asm volatile(
                    "mma.sync.aligned.m16n8k8.row.col.f32.tf32.tf32.f32 "
                    "{%0,%1,%2,%3}, {%4,%5,%6,%7}, {%8,%9}, {%0,%1,%2,%3};"
                    : "+f"(acc2[mi][ni][0]), "+f"(acc2[mi][ni][1]),
                      "+f"(acc2[mi][ni][2]), "+f"(acc2[mi][ni][3])
                    : "r"(af[mi][0]), "r"(af[mi][1]), "r"(af[mi][2]), "r"(af[mi][3]),
                      "r"(b0), "r"(b1));
            }
        }
    }

    // write per-bn partial
    float* part = g_part_h + (size_t)blockIdx.x * N_NODES * F_OUT;
#pragma unroll
    for (int mi = 0; mi < 2; mi++) {
#pragma unroll
        for (int ni = 0; ni < 5; ni++) {
            int col = ni * 8 + tig * 2;
            int r0 = bm + wrow + mi * 16 + group;
            if (r0 < N_NODES)
                *(float2*)(part + (size_t)r0 * F_OUT + col) =
                    make_float2(acc2[mi][ni][0], acc2[mi][ni][1]);
            int r1 = r0 + 8;
            if (r1 < N_NODES)
                *(float2*)(part + (size_t)r1 * F_OUT + col) =
                    make_float2(acc2[mi][ni][2], acc2[mi][ni][3]);
        }
    }
}

// ---------------- combine: h = b2 + sum of 2 partials ----------------
__global__ __launch_bounds__(256) void combine_kernel(const float* __restrict__ b2) {
    int idx = blockIdx.x * 256 + threadIdx.x;
    const int TOT = N_NODES * F_OUT / 4;
    if (idx >= TOT) return;
    const float4* p = (const float4*)g_part_h;
    const size_t STRIDE4 = (size_t)N_NODES * F_OUT / 4;
    float4 a = p[idx];
    float4 b = p[idx + STRIDE4];
    float4 bz = ((const float4*)b2)[idx % (F_OUT / 4)];
    float4 r;
    r.x = a.x + b.x + bz.x;
    r.y = a.y + b.y + bz.y;
    r.z = a.z + b.z + bz.z;
    r.w = a.w + b.w + bz.w;
    ((float4*)g_h)[idx] = r;
}

// ---------------- AMP: warp per node, 3 edge-groups of 10 lanes ----------
__global__ __launch_bounds__(256) void amp_kernel(const float4* __restrict__ xk4,
                                                  float4* __restrict__ xout4,
                                                  float* __restrict__ sout) {
    int node = (blockIdx.x * 256 + threadIdx.x) >> 5;
    int lane = threadIdx.x & 31;
    if (node >= N_NODES) return;
    int g = lane >= 30 ? 3 : (lane >= 20 ? 2 : (lane >= 10 ? 1 : 0));
    int sub = lane - g * 10;
    if (g == 3) sub = lane - 30;
    bool act = lane < 30;

    float4 xq = make_float4(0.f, 0.f, 0.f, 0.f);
    float4 accA = make_float4(0.f, 0.f, 0.f, 0.f);
    float4 accB = make_float4(0.f, 0.f, 0.f, 0.f);
    if (g == 0) {
        xq = xk4[(size_t)node * 10 + sub];
        float dv = g_dinv[node];
        float wself = dv * dv;
        accA.x = wself * xq.x; accA.y = wself * xq.y;
        accA.z = wself * xq.z; accA.w = wself * xq.w;
    }

    int beg = g_rowstart[node];
    int cnt = g_count[node];
    int base = 0;
    for (; base + 6 <= cnt; base += 6) {
        int iA = base + g, iB = base + 3 + g;
        float2 swA = act ? g_csr_sw[beg + iA] : make_float2(0.f, 0.f);
        float2 swB = act ? g_csr_sw[beg + iB] : make_float2(0.f, 0.f);
        int sA = act ? __float_as_int(swA.x) : 0;
        int sB = act ? __float_as_int(swB.x) : 0;
        float4 xA = xk4[(size_t)sA * 10 + sub];
        float4 xB = xk4[(size_t)sB * 10 + sub];
        accA.x += swA.y * xA.x; accA.y += swA.y * xA.y;
        accA.z += swA.y * xA.z; accA.w += swA.y * xA.w;
        accB.x += swB.y * xB.x; accB.y += swB.y * xB.y;
        accB.z += swB.y * xB.z; accB.w += swB.y * xB.w;
    }
    for (; base < cnt; base += 3) {
        int idx = base + g;
        bool v = act && (idx < cnt);
        float2 sw = v ? g_csr_sw[beg + idx] : make_float2(0.f, 0.f);
        int s = v ? __float_as_int(sw.x) : 0;
        float4 xs = xk4[(size_t)s * 10 + sub];
        accA.x += sw.y * xs.x; accA.y += sw.y * xs.y;
        accA.z += sw.y * xs.z; accA.w += sw.y * xs.w;
    }
    accA.x += accB.x; accA.y += accB.y; accA.z += accB.z; accA.w += accB.w;

    {
        float t1, t2;
        t1 = __shfl_down_sync(0xffffffffu, accA.x, 10);
        t2 = __shfl_down_sync(0xffffffffu, accA.x, 20);
        accA.x += t1 + t2;
        t1 = __shfl_down_sync(0xffffffffu, accA.y, 10);
        t2 = __shfl_down_sync(0xffffffffu, accA.y, 20);
        accA.y += t1 + t2;
        t1 = __shfl_down_sync(0xffffffffu, accA.z, 10);
        t2 = __shfl_down_sync(0xffffffffu, accA.z, 20);
        accA.z += t1 + t2;
        t1 = __shfl_down_sync(0xffffffffu, accA.w, 10);
        t2 = __shfl_down_sync(0xffffffffu, accA.w, 20);
        accA.w += t1 + t2;
    }

    float4 hq = make_float4(0.f, 0.f, 0.f, 0.f);
    float4 d = make_float4(0.f, 0.f, 0.f, 0.f);
    float ss = 0.f;
    if (g == 0) {
        hq = ((const float4*)g_h)[(size_t)node * 10 + sub];
        float4 y;
        y.x = xq.x - COEF * (xq.x - accA.x);
        y.y = xq.y - COEF * (xq.y - accA.y);
        y.z = xq.z - COEF * (xq.z - accA.z);
        y.w = xq.w - COEF * (xq.w - accA.w);
        d.x = y.x - hq.x; d.y = y.y - hq.y; d.z = y.z - hq.z; d.w = y.w - hq.w;
        ss = d.x * d.x + d.y * d.y + d.z * d.z + d.w * d.w;
    }
#pragma unroll
    for (int o = 16; o > 0; o >>= 1) ss += __shfl_xor_sync(0xffffffffu, ss, o);
    float rn = sqrtf(ss);
    float score = (rn > 0.f) ? fmaxf(rn - LAM, 0.f) / rn : 0.f;

    if (g == 0) {
        float4 r;
        r.x = hq.x + score * d.x; r.y = hq.y + score * d.y;
        r.z = hq.z + score * d.z; r.w = hq.w + score * d.w;
        xout4[(size_t)node * 10 + sub] = r;
    }
    if (sout && lane == 0) sout[node] = score;
}

// ---------------- log_softmax: warp per row ----------------
__global__ __launch_bounds__(256) void finalize_kernel(const float* __restrict__ xk,
                                                       float* __restrict__ out) {
    int row = (blockIdx.x * 256 + threadIdx.x) >> 5;
    int lane = threadIdx.x & 31;
    if (row >= N_NODES) return;
    const float* xr = xk + (size_t)row * F_OUT;
    float v0 = xr[lane];
    bool has1 = (lane + 32 < F_OUT);
    float v1 = has1 ? xr[lane + 32] : -INFINITY;
    float m = fmaxf(v0, v1);
#pragma unroll
    for (int o = 16; o > 0; o >>= 1) m = fmaxf(m, __shfl_xor_sync(0xffffffffu, m, o));
    float e = expf(v0 - m) + (has1 ? expf(v1 - m) : 0.f);
#pragma unroll
    for (int o = 16; o > 0; o >>= 1) e += __shfl_xor_sync(0xffffffffu, e, o);
    float lse = m + logf(e);
    out[(size_t)row * F_OUT + lane] = v0 - lse;
    if (has1) out[(size_t)row * F_OUT + 32 + lane] = v1 - lse;
}

// ---------------- launch ----------------
extern "C" void kernel_launch(void* const* d_in, const int* in_sizes, int n_in,
                              void* d_out, int out_size) {
    const float* x   = (const float*)d_in[0];
    const float* W1  = (const float*)d_in[1];
    const float* b1  = (const float*)d_in[2];
    const float* W2  = (const float*)d_in[3];
    const float* b2  = (const float*)d_in[4];
    const int* esrc  = (const int*)d_in[5];
    const int* edst  = (const int*)d_in[6];
    float* out = (float*)d_out;

    float *ph, *pxa, *pxb;
    int *pcount, *prowstart, *ppart, *ppscan;
    cudaGetSymbolAddress((void**)&ph,  g_h);
    cudaGetSymbolAddress((void**)&pxa, g_xa);
    cudaGetSymbolAddress((void**)&pxb, g_xb);
    cudaGetSymbolAddress((void**)&pcount,    g_count);
    cudaGetSymbolAddress((void**)&prowstart, g_rowstart);
    cudaGetSymbolAddress((void**)&ppart,     g_part);
    cudaGetSymbolAddress((void**)&ppscan,    g_pscan);

    static cudaStream_t s1 = nullptr;
    static cudaEvent_t evFork = nullptr, evJoin = nullptr;
    if (!s1) {
        cudaStreamCreateWithFlags(&s1, cudaStreamNonBlocking);
        cudaEventCreateWithFlags(&evFork, cudaEventDisableTiming);
        cudaEventCreateWithFlags(&evJoin, cudaEventDisableTiming);
        cudaFuncSetAttribute(gemm1_mma_kernel,
                             cudaFuncAttributeMaxDynamicSharedMemorySize, DSMEM_BYTES);
    }

    const int NB = (N_NODES + 255) / 256;

    // fork: setup chain on s1, MLP on main stream
    cudaEventRecord(evFork, 0);
    cudaStreamWaitEvent(s1, evFork, 0);

    zero_kernel<<<NB, 256, 0, s1>>>();
    hist_kernel<<<1024, 256, 0, s1>>>(edst);
    dinv_kernel<<<NB, 256, 0, s1>>>();

    // issue-order slot 3: fused MLP (profiled), on main stream
    dim3 g1grid(F_HID / BN, (N_NODES + BM - 1) / BM);
    gemm1_mma_kernel<<<g1grid, 256, DSMEM_BYTES>>>(x, W1, b1, W2);

    const int SCAN_BLOCKS = (N_NODES + 511) / 512;
    scan_block<<<SCAN_BLOCKS, 256, 0, s1>>>(pcount, prowstart, ppart, N_NODES);
    scan_block<<<1, 256, 0, s1>>>(ppart, ppscan, ppart, SCAN_BLOCKS);
    add_offsets<<<NB, 256, 0, s1>>>(prowstart, ppscan, N_NODES);
    scatter_kernel<<<1024, 256, 0, s1>>>(esrc, edst);
    cudaEventRecord(evJoin, s1);

    combine_kernel<<<(N_NODES * F_OUT / 4 + 255) / 256, 256>>>(b2);

    // join before AMP (needs CSR + h)
    cudaStreamWaitEvent(0, evJoin, 0);

    float* score_out = nullptr;
    float* lsm_out = out;
    if (out_size >= N_NODES * F_OUT + N_NODES) {
        score_out = out + (size_t)N_NODES * F_OUT;
    } else if (out_size == N_NODES) {
        score_out = out;
        lsm_out = nullptr;
    }

    const int AMP_BLOCKS = (N_NODES * 32 + 255) / 256;
    const float* xin = ph;
    float* bufs[2] = {pxa, pxb};
    for (int it = 0; it < K_ITERS; it++) {
        float* xout = bufs[it & 1];
        float* so = (it == K_ITERS - 1) ? score_out : nullptr;
        amp_kernel<<<AMP_BLOCKS, 256>>>((const float4*)xin, (float4*)xout, so);
        xin = xout;
    }

    if (lsm_out)
        finalize_kernel<<<AMP_BLOCKS, 256>>>(xin, lsm_out);
}